// round 1
// baseline (speedup 1.0000x reference)
#include <cuda_runtime.h>
#include <cstdint>

// ---------------------------------------------------------------------------
// Radon transform, 180 angles, 512x512, batch 2.
//
// out[n,0,c,t] = (1/512) * sum_r bilinear(img_n ; ix(t,r,c), iy(t,r,c))
//   ix = 256*(cos t * base_c + sin t * base_r) + 255.5
//   iy = 256*(-sin t * base_c + cos t * base_r) + 255.5
//   base_i = (2i+1)/512 - 1  ->  ix(r) = A_c + s*(r-255.5), iy(r) = B_c + ct*(r-255.5)
//
// Strategy:
//  * Both batch images share identical coordinates/weights. Preprocess into a
//    zero-padded interleaved float4 array:
//       pad[ky][kx] = (b0[y][x], b1[y][x], b0[y][x+1], b1[y][x+1]),  y=ky-2, x=kx-2
//    One LDG.128 yields v00/v01 for BOTH batches; row y0+1 is a constant offset.
//  * Per-thread analytic clip of r to the segment intersecting [-1,512]^2
//    (everything outside contributes exactly 0; padded zeros absorb the +-1
//    step of slop from floor/ceil of the bounds). No per-texel predication.
//  * Bilinear lerp in packed fp32x2 (batch0 in lane lo, batch1 in lane hi).
// ---------------------------------------------------------------------------

#define PW   517                 // padded dim: x,y in [-2, 514]; safe for y0+1 <= 516
#define NPIX (PW * PW)
#define NT   180
#define W    512

__device__ float4 g_pad[NPIX];   // 4.28 MB static scratch (resident in L2)

typedef unsigned long long u64;

__device__ __forceinline__ u64 pk2(float lo, float hi) {
    u64 r; asm("mov.b64 %0, {%1, %2};" : "=l"(r) : "f"(lo), "f"(hi)); return r;
}
__device__ __forceinline__ void unpk2(u64 v, float& lo, float& hi) {
    asm("mov.b64 {%0, %1}, %2;" : "=f"(lo), "=f"(hi) : "l"(v));
}
__device__ __forceinline__ u64 ffma2(u64 a, u64 b, u64 c) {
    u64 d; asm("fma.rn.f32x2 %0, %1, %2, %3;" : "=l"(d) : "l"(a), "l"(b), "l"(c)); return d;
}
__device__ __forceinline__ u64 fadd2(u64 a, u64 b) {
    u64 d; asm("add.rn.f32x2 %0, %1, %2;" : "=l"(d) : "l"(a), "l"(b)); return d;
}

// Build padded interleaved image. One thread per padded float4 entry.
__global__ void build_pad(const float* __restrict__ x) {
    int idx = blockIdx.x * blockDim.x + threadIdx.x;
    if (idx >= NPIX) return;
    int ky = idx / PW;
    int kx = idx - ky * PW;
    int y  = ky - 2;
    int x0 = kx - 2;
    int x1 = kx - 1;
    float a0 = 0.f, a1 = 0.f, b0 = 0.f, b1 = 0.f;
    if (y >= 0 && y < W) {
        const float* r0 = x + y * W;             // batch 0
        const float* r1 = x + W * W + y * W;     // batch 1
        if (x0 >= 0 && x0 < W) { a0 = r0[x0]; a1 = r1[x0]; }
        if (x1 >= 0 && x1 < W) { b0 = r0[x1]; b1 = r1[x1]; }
    }
    g_pad[idx] = make_float4(a0, a1, b0, b1);
}

__global__ __launch_bounds__(128) void radon_kernel(float* __restrict__ out) {
    int c = blockIdx.x * 128 + threadIdx.x;   // detector column, 0..511
    int t = blockIdx.y;                       // angle, 0..179

    float th = (float)t * 0.017453292519943295f;
    float s  = sinf(th);                      // >= 0 for t in [0,180)
    float ct = cosf(th);

    float base_c = (float)(2 * c + 1) * (1.0f / 512.0f) - 1.0f;
    // coordinates at r = 0
    float ix0 = fmaf(-255.5f, s,  fmaf( 256.0f * ct, base_c, 255.5f));
    float iy0 = fmaf(-255.5f, ct, fmaf(-256.0f * s,  base_c, 255.5f));

    // ---- clip r to the segment where (ix,iy) stays inside [-1, 512]^2 ----
    float sx  = fmaxf(s, 1e-8f);
    float sy  = (fabsf(ct) < 1e-8f) ? ((ct < 0.f) ? -1e-8f : 1e-8f) : ct;
    float ivx = 1.0f / sx;
    float ivy = 1.0f / sy;
    float tx1 = (-1.0f  - ix0) * ivx;
    float tx2 = (512.0f - ix0) * ivx;
    float ty1 = (-1.0f  - iy0) * ivy;
    float ty2 = (512.0f - iy0) * ivy;
    float rminf = fmaxf(fmaxf(fminf(tx1, tx2), fminf(ty1, ty2)), 0.0f);
    float rmaxf = fminf(fminf(fmaxf(tx1, tx2), fmaxf(ty1, ty2)), 511.0f);
    rminf = fminf(rminf, 1024.0f);    // keep int conversion safe
    rmaxf = fmaxf(rmaxf, -2.0f);
    int rlo = (int)floorf(rminf);     // +-1 step of slop is absorbed by padding
    int rhi = (int)ceilf(rmaxf);

    // padded-space coordinates (always >= 0 inside the loop -> trunc == floor)
    float ix0p = ix0 + 2.0f;
    float iy0p = iy0 + 2.0f;

    const float4* __restrict__ pp = g_pad;
    const u64 M1 = pk2(-1.0f, -1.0f);
    u64 acc = pk2(0.0f, 0.0f);

#pragma unroll 4
    for (int r = rlo; r <= rhi; ++r) {
        float rf  = (float)r;
        float pix = fmaf(rf, s,  ix0p);
        float piy = fmaf(rf, ct, iy0p);
        int   x0  = (int)pix;
        int   y0  = (int)piy;
        float fx  = pix - (float)x0;
        float fy  = piy - (float)y0;

        int o = y0 * PW + x0;
        float4 va = __ldg(pp + o);        // row y0:   (b0@x, b1@x, b0@x+1, b1@x+1)
        float4 vb = __ldg(pp + o + PW);   // row y0+1

        u64 v00 = pk2(va.x, va.y);
        u64 v01 = pk2(va.z, va.w);
        u64 v10 = pk2(vb.x, vb.y);
        u64 v11 = pk2(vb.z, vb.w);
        u64 fxp = pk2(fx, fx);
        u64 fyp = pk2(fy, fy);

        u64 d0 = ffma2(v00, M1, v01);     // v01 - v00
        u64 l0 = ffma2(fxp, d0, v00);
        u64 d1 = ffma2(v10, M1, v11);     // v11 - v10
        u64 l1 = ffma2(fxp, d1, v10);
        u64 dl = ffma2(l0, M1, l1);       // l1 - l0
        u64 vv = ffma2(fyp, dl, l0);      // bilinear value, both batches
        acc = fadd2(acc, vv);
    }

    float a0, a1;
    unpk2(acc, a0, a1);
    const float inv = 1.0f / 512.0f;
    int o0 = c * NT + t;
    out[o0]            = a0 * inv;        // batch 0
    out[W * NT + o0]   = a1 * inv;        // batch 1
}

extern "C" void kernel_launch(void* const* d_in, const int* in_sizes, int n_in,
                              void* d_out, int out_size) {
    const float* x = (const float*)d_in[0];
    float* out = (float*)d_out;

    build_pad<<<(NPIX + 255) / 256, 256>>>(x);

    dim3 grid(W / 128, NT);
    radon_kernel<<<grid, 128>>>(out);
}